// round 2
// baseline (speedup 1.0000x reference)
#include <cuda_runtime.h>

// Problem constants
#define NP 65536
#define KC 1024
#define DD 512

#define BM 128
#define BN 128
#define BK 16
#define NT 256

// Scratch (allocation-free rule: __device__ globals)
__device__ float  g_x2[NP];
__device__ float  g_c2[KC];
__device__ double g_loss;

// ---------------------------------------------------------------------------
// Kernel 1: row norms computed as STRICT SEQUENTIAL  acc = rn(acc + rn(v*v))
// over k ascending — replicating XLA's order-strict row reduction bits.
// Blocks 0..255 handle x rows (256 rows/block); blocks 256..259 handle centers.
// A SMEM-staged transpose keeps global loads coalesced while each thread sums
// its own row sequentially.
// ---------------------------------------------------------------------------
__global__ __launch_bounds__(256) void prep_kernel(const float* __restrict__ x,
                                                   const float* __restrict__ cen) {
    __shared__ float sm[256][33];
    const int tid  = threadIdx.x;
    const int warp = tid >> 5;
    const int lane = tid & 31;

    if (blockIdx.x == 0 && tid == 0) g_loss = 0.0;

    const float* src;
    int row0, nrows;
    if (blockIdx.x < 256) { src = x;   row0 = blockIdx.x * 256;         nrows = 256; }
    else                  { src = cen; row0 = (blockIdx.x - 256) * 256; nrows = 256; }

    float acc = 0.f;
    for (int kc = 0; kc < DD / 32; kc++) {
        // coalesced load: warp w loads rows [w*32, w*32+32), 32 k's per row
#pragma unroll 4
        for (int rr = 0; rr < 32; rr++) {
            int r = warp * 32 + rr;
            sm[r][lane] = src[(size_t)(row0 + r) * DD + kc * 32 + lane];
        }
        __syncthreads();
        // sequential accumulate: k ascending, separate rn mul + rn add
#pragma unroll
        for (int k = 0; k < 32; k++) {
            float v = sm[tid][k];
            acc = __fadd_rn(acc, __fmul_rn(v, v));
        }
        __syncthreads();
    }
    (void)nrows;
    if (blockIdx.x < 256) g_x2[row0 + tid] = acc;
    else                  g_c2[row0 + tid] = acc;
}

// ---------------------------------------------------------------------------
// Kernel 2: fused SGEMM (x @ centers^T) + exact reference-formula distance
// + argmin + loss gather.
// dot accumulated with ONE fp32 accumulator per element, fused FMA, k strictly
// ascending (matches Eigen/oneDNN/cublas accumulation order bit-for-bit).
// distance = rn( rn(x2 - 2*t) + c2 )   [2*t exact]
// ---------------------------------------------------------------------------
__global__ __launch_bounds__(NT) void kmeans_main(
    const float* __restrict__ x, const int* __restrict__ y,
    const float* __restrict__ cen, float* __restrict__ out) {
    __shared__ float  xs[2][BK][BM];
    __shared__ float  cs[2][BK][BN];
    __shared__ float  c2s[KC];
    __shared__ double lred[NT];

    const int tid  = threadIdx.x;
    const int row0 = blockIdx.x * BM;
    const int trow = tid >> 4;   // 0..15
    const int tcol = tid & 15;   // 0..15

    for (int i = tid; i < KC; i += NT) c2s[i] = g_c2[i];

    int    ylab[8];
    float  x2r[8];
    float  bestd[8];
    int    bidx[8];
    double syd[8];
#pragma unroll
    for (int i = 0; i < 8; i++) {
        int row  = row0 + trow * 8 + i;
        ylab[i]  = y[row];
        x2r[i]   = g_x2[row];
        bestd[i] = 3.4e38f;
        bidx[i]  = 0;
        syd[i]   = 0.0;
    }
    __syncthreads();

    const float4* xg = (const float4*)x;
    const float4* cg = (const float4*)cen;

    for (int ct = 0; ct < KC / BN; ct++) {
        const int cbase = ct * BN;
        float acc[8][8];
#pragma unroll
        for (int i = 0; i < 8; i++)
#pragma unroll
            for (int j = 0; j < 8; j++) acc[i][j] = 0.f;

        float4 px[2], pc[2];
#pragma unroll
        for (int s = 0; s < 2; s++) {
            int f = tid + s * NT;
            int r = f >> 2, d4 = f & 3;
            px[s] = xg[(size_t)(row0 + r) * (DD / 4) + d4];
            pc[s] = cg[(size_t)(cbase + r) * (DD / 4) + d4];
        }
#pragma unroll
        for (int s = 0; s < 2; s++) {
            int f = tid + s * NT;
            int r = f >> 2, d4 = f & 3;
            xs[0][d4 * 4 + 0][r] = px[s].x;
            xs[0][d4 * 4 + 1][r] = px[s].y;
            xs[0][d4 * 4 + 2][r] = px[s].z;
            xs[0][d4 * 4 + 3][r] = px[s].w;
            cs[0][d4 * 4 + 0][r] = pc[s].x;
            cs[0][d4 * 4 + 1][r] = pc[s].y;
            cs[0][d4 * 4 + 2][r] = pc[s].z;
            cs[0][d4 * 4 + 3][r] = pc[s].w;
        }
        __syncthreads();

        int buf = 0;
        for (int dstep = 0; dstep < DD / BK; dstep++) {
            if (dstep + 1 < DD / BK) {
#pragma unroll
                for (int s = 0; s < 2; s++) {
                    int f = tid + s * NT;
                    int r = f >> 2, d4 = f & 3;
                    px[s] = xg[(size_t)(row0 + r) * (DD / 4) + (dstep + 1) * 4 + d4];
                    pc[s] = cg[(size_t)(cbase + r) * (DD / 4) + (dstep + 1) * 4 + d4];
                }
            }
#pragma unroll
            for (int d = 0; d < BK; d++) {   // k strictly ascending
                float4 a0 = *(const float4*)&xs[buf][d][trow * 8];
                float4 a1 = *(const float4*)&xs[buf][d][trow * 8 + 4];
                float4 b0 = *(const float4*)&cs[buf][d][tcol * 8];
                float4 b1 = *(const float4*)&cs[buf][d][tcol * 8 + 4];
                float a[8] = {a0.x, a0.y, a0.z, a0.w, a1.x, a1.y, a1.z, a1.w};
                float b[8] = {b0.x, b0.y, b0.z, b0.w, b1.x, b1.y, b1.z, b1.w};
#pragma unroll
                for (int i = 0; i < 8; i++)
#pragma unroll
                    for (int j = 0; j < 8; j++)
                        acc[i][j] = fmaf(a[i], b[j], acc[i][j]);  // single-acc FFMA chain
            }
            if (dstep + 1 < DD / BK) {
                int nb = buf ^ 1;
#pragma unroll
                for (int s = 0; s < 2; s++) {
                    int f = tid + s * NT;
                    int r = f >> 2, d4 = f & 3;
                    xs[nb][d4 * 4 + 0][r] = px[s].x;
                    xs[nb][d4 * 4 + 1][r] = px[s].y;
                    xs[nb][d4 * 4 + 2][r] = px[s].z;
                    xs[nb][d4 * 4 + 3][r] = px[s].w;
                    cs[nb][d4 * 4 + 0][r] = pc[s].x;
                    cs[nb][d4 * 4 + 1][r] = pc[s].y;
                    cs[nb][d4 * 4 + 2][r] = pc[s].z;
                    cs[nb][d4 * 4 + 3][r] = pc[s].w;
                }
            }
            __syncthreads();
            buf ^= 1;
        }

        // epilogue: distance = rn( rn(x2 - 2t) + c2 ), argmin first-occurrence
#pragma unroll
        for (int i = 0; i < 8; i++) {
#pragma unroll
            for (int j = 0; j < 8; j++) {
                int   col = cbase + tcol * 8 + j;
                float t   = acc[i][j];
                float s2  = 2.0f * t;                       // exact
                float u   = __fsub_rn(x2r[i], s2);          // rn(x2 - 2t)
                float dst = __fadd_rn(u, c2s[col]);         // rn(u + c2)
                if (dst < bestd[i]) { bestd[i] = dst; bidx[i] = col; }
                if (col == ylab[i]) syd[i] = (double)dst;
            }
        }
    }

    // cross-thread reduction: 16 lanes (same trow) cover all K columns
    double lossp = 0.0;
#pragma unroll
    for (int i = 0; i < 8; i++) {
        float  v   = bestd[i];
        int    idx = bidx[i];
        double s   = syd[i];
#pragma unroll
        for (int off = 8; off >= 1; off >>= 1) {
            float  v2 = __shfl_xor_sync(0xffffffffu, v, off);
            int    i2 = __shfl_xor_sync(0xffffffffu, idx, off);
            double s2 = __shfl_xor_sync(0xffffffffu, s, off);
            s += s2;
            if (v2 < v || (v2 == v && i2 < idx)) { v = v2; idx = i2; }
        }
        if (tcol == 0) {
            int row = row0 + trow * 8 + i;
            out[1 + row] = (float)idx;  // ynew
            lossp += s;                 // distance[row, y[row]]
        }
    }
    lred[tid] = lossp;
    __syncthreads();
    for (int sdiv = NT / 2; sdiv > 0; sdiv >>= 1) {
        if (tid < sdiv) lred[tid] += lred[tid + sdiv];
        __syncthreads();
    }
    if (tid == 0) atomicAdd(&g_loss, lred[0]);
}

// Kernel 3: write scalar loss; zero any padding in out.
__global__ void finalize_kernel(float* __restrict__ out, int out_size) {
    int t = blockIdx.x * blockDim.x + threadIdx.x;
    if (t == 0) out[0] = (float)g_loss;
    for (int i = 1 + NP + t; i < out_size; i += blockDim.x * gridDim.x) out[i] = 0.f;
}

extern "C" void kernel_launch(void* const* d_in, const int* in_sizes, int n_in,
                              void* d_out, int out_size) {
    const float* x = nullptr;
    const int*   y = nullptr;
    const float* cen = nullptr;
    for (int i = 0; i < n_in; i++) {
        if (in_sizes[i] == NP * DD)      x = (const float*)d_in[i];
        else if (in_sizes[i] == KC * DD) cen = (const float*)d_in[i];
        else if (in_sizes[i] == NP)      y = (const int*)d_in[i];
    }
    float* out = (float*)d_out;

    prep_kernel<<<256 + KC / 256, 256>>>(x, cen);
    kmeans_main<<<NP / BM, NT>>>(x, y, cen, out);
    finalize_kernel<<<1, 256>>>(out, out_size);
}

// round 3
// speedup vs baseline: 1.2973x; 1.2973x over previous
#include <cuda_runtime.h>

// Problem constants
#define NP 65536
#define KC 1024
#define DD 512

#define BM 128
#define BN 128
#define BK 16
#define NT 256

// Scratch (allocation-free rule: __device__ globals)
__device__ float  g_x2[NP];
__device__ float  g_c2[KC];
__device__ double g_loss;

__device__ __forceinline__ unsigned long long pk2(float lo, float hi) {
    unsigned long long r;
    asm("mov.b64 %0, {%1, %2};" : "=l"(r) : "f"(lo), "f"(hi));
    return r;
}
__device__ __forceinline__ void upk2(unsigned long long v, float& lo, float& hi) {
    asm("mov.b64 {%0, %1}, %2;" : "=f"(lo), "=f"(hi) : "l"(v));
}
// Packed dual FMA: lane0/lane1 are INDEPENDENT output elements (two rows, same
// column). Each lane is a single-accumulator fused-FMA chain, k ascending —
// bit-identical to the scalar fmaf chain the reference produces per element.
__device__ __forceinline__ void fma2(unsigned long long& d, unsigned long long a,
                                     unsigned long long b) {
    asm("fma.rn.f32x2 %0, %1, %2, %0;" : "+l"(d) : "l"(a), "l"(b));
}

// ---------------------------------------------------------------------------
// Kernel 1: row norms, STRICT SEQUENTIAL  acc = rn(acc + rn(v*v)), k ascending.
// ---------------------------------------------------------------------------
__global__ __launch_bounds__(256) void prep_kernel(const float* __restrict__ x,
                                                   const float* __restrict__ cen) {
    __shared__ float sm[256][33];
    const int tid  = threadIdx.x;
    const int warp = tid >> 5;
    const int lane = tid & 31;

    if (blockIdx.x == 0 && tid == 0) g_loss = 0.0;

    const float* src;
    int row0;
    if (blockIdx.x < 256) { src = x;   row0 = blockIdx.x * 256; }
    else                  { src = cen; row0 = (blockIdx.x - 256) * 256; }

    float acc = 0.f;
    for (int kc = 0; kc < DD / 32; kc++) {
#pragma unroll 4
        for (int rr = 0; rr < 32; rr++) {
            int r = warp * 32 + rr;
            sm[r][lane] = src[(size_t)(row0 + r) * DD + kc * 32 + lane];
        }
        __syncthreads();
#pragma unroll
        for (int k = 0; k < 32; k++) {
            float v = sm[tid][k];
            acc = __fadd_rn(acc, __fmul_rn(v, v));
        }
        __syncthreads();
    }
    if (blockIdx.x < 256) g_x2[row0 + tid] = acc;
    else                  g_c2[row0 + tid] = acc;
}

// ---------------------------------------------------------------------------
// Kernel 2: fused SGEMM (x @ centers^T) via FFMA2 (row-packed) + exact
// reference-formula distance + argmin + loss gather.
// ---------------------------------------------------------------------------
__global__ __launch_bounds__(NT, 1) void kmeans_main(
    const float* __restrict__ x, const int* __restrict__ y,
    const float* __restrict__ cen, float* __restrict__ out) {
    __shared__ float  xs[2][BK][BM];
    __shared__ float  cs[2][BK][BN];
    __shared__ float  c2s[KC];
    __shared__ double lred[NT];

    const int tid  = threadIdx.x;
    const int row0 = blockIdx.x * BM;
    const int trow = tid >> 4;   // 0..15  -> rows trow*8 .. trow*8+7
    const int tcol = tid & 15;   // 0..15  -> cols tcol*8 .. tcol*8+7

    for (int i = tid; i < KC; i += NT) c2s[i] = g_c2[i];

    int    ylab[8];
    float  x2r[8];
    float  bestd[8];
    int    bidx[8];
    double syd[8];
#pragma unroll
    for (int i = 0; i < 8; i++) {
        int row  = row0 + trow * 8 + i;
        ylab[i]  = y[row];
        x2r[i]   = g_x2[row];
        bestd[i] = 3.4e38f;
        bidx[i]  = 0;
        syd[i]   = 0.0;
    }
    __syncthreads();

    const float4* xg = (const float4*)x;
    const float4* cg = (const float4*)cen;

    for (int ct = 0; ct < KC / BN; ct++) {
        const int cbase = ct * BN;
        // acc[ip][j]: packed pair = (row 2ip, row 2ip+1) x column j
        unsigned long long acc[4][8];
#pragma unroll
        for (int ip = 0; ip < 4; ip++)
#pragma unroll
            for (int j = 0; j < 8; j++) acc[ip][j] = 0ull;

        float4 px[2], pc[2];
#pragma unroll
        for (int s = 0; s < 2; s++) {
            int f = tid + s * NT;
            int r = f >> 2, d4 = f & 3;
            px[s] = xg[(size_t)(row0 + r) * (DD / 4) + d4];
            pc[s] = cg[(size_t)(cbase + r) * (DD / 4) + d4];
        }
#pragma unroll
        for (int s = 0; s < 2; s++) {
            int f = tid + s * NT;
            int r = f >> 2, d4 = f & 3;
            xs[0][d4 * 4 + 0][r] = px[s].x;
            xs[0][d4 * 4 + 1][r] = px[s].y;
            xs[0][d4 * 4 + 2][r] = px[s].z;
            xs[0][d4 * 4 + 3][r] = px[s].w;
            cs[0][d4 * 4 + 0][r] = pc[s].x;
            cs[0][d4 * 4 + 1][r] = pc[s].y;
            cs[0][d4 * 4 + 2][r] = pc[s].z;
            cs[0][d4 * 4 + 3][r] = pc[s].w;
        }
        __syncthreads();

        int buf = 0;
        for (int dstep = 0; dstep < DD / BK; dstep++) {
            if (dstep + 1 < DD / BK) {
#pragma unroll
                for (int s = 0; s < 2; s++) {
                    int f = tid + s * NT;
                    int r = f >> 2, d4 = f & 3;
                    px[s] = xg[(size_t)(row0 + r) * (DD / 4) + (dstep + 1) * 4 + d4];
                    pc[s] = cg[(size_t)(cbase + r) * (DD / 4) + (dstep + 1) * 4 + d4];
                }
            }
#pragma unroll
            for (int d = 0; d < BK; d++) {   // k strictly ascending
                // A rows: 8 floats -> 4 naturally-paired 64-bit operands
                ulonglong2 va = *(const ulonglong2*)&xs[buf][d][trow * 8];
                ulonglong2 vb = *(const ulonglong2*)&xs[buf][d][trow * 8 + 4];
                unsigned long long xp[4] = {va.x, va.y, vb.x, vb.y};
                // B cols: 8 floats, each replicated into both lanes
                float4 b0 = *(const float4*)&cs[buf][d][tcol * 8];
                float4 b1 = *(const float4*)&cs[buf][d][tcol * 8 + 4];
                unsigned long long cp[8];
                cp[0] = pk2(b0.x, b0.x);
                cp[1] = pk2(b0.y, b0.y);
                cp[2] = pk2(b0.z, b0.z);
                cp[3] = pk2(b0.w, b0.w);
                cp[4] = pk2(b1.x, b1.x);
                cp[5] = pk2(b1.y, b1.y);
                cp[6] = pk2(b1.z, b1.z);
                cp[7] = pk2(b1.w, b1.w);
#pragma unroll
                for (int ip = 0; ip < 4; ip++)
#pragma unroll
                    for (int j = 0; j < 8; j++) fma2(acc[ip][j], xp[ip], cp[j]);
            }
            if (dstep + 1 < DD / BK) {
                int nb = buf ^ 1;
#pragma unroll
                for (int s = 0; s < 2; s++) {
                    int f = tid + s * NT;
                    int r = f >> 2, d4 = f & 3;
                    xs[nb][d4 * 4 + 0][r] = px[s].x;
                    xs[nb][d4 * 4 + 1][r] = px[s].y;
                    xs[nb][d4 * 4 + 2][r] = px[s].z;
                    xs[nb][d4 * 4 + 3][r] = px[s].w;
                    cs[nb][d4 * 4 + 0][r] = pc[s].x;
                    cs[nb][d4 * 4 + 1][r] = pc[s].y;
                    cs[nb][d4 * 4 + 2][r] = pc[s].z;
                    cs[nb][d4 * 4 + 3][r] = pc[s].w;
                }
            }
            __syncthreads();
            buf ^= 1;
        }

        // epilogue: distance = rn( rn(x2 - 2t) + c2 ), argmin first-occurrence
#pragma unroll
        for (int i = 0; i < 8; i++) {
#pragma unroll
            for (int j = 0; j < 8; j++) {
                float lo, hi;
                upk2(acc[i >> 1][j], lo, hi);
                float t   = (i & 1) ? hi : lo;
                int   col = cbase + tcol * 8 + j;
                float s2  = 2.0f * t;                       // exact
                float u   = __fsub_rn(x2r[i], s2);          // rn(x2 - 2t)
                float dst = __fadd_rn(u, c2s[col]);         // rn(u + c2)
                if (dst < bestd[i]) { bestd[i] = dst; bidx[i] = col; }
                if (col == ylab[i]) syd[i] = (double)dst;
            }
        }
    }

    // cross-thread reduction: 16 lanes (same trow) cover all K columns
    double lossp = 0.0;
#pragma unroll
    for (int i = 0; i < 8; i++) {
        float  v   = bestd[i];
        int    idx = bidx[i];
        double s   = syd[i];
#pragma unroll
        for (int off = 8; off >= 1; off >>= 1) {
            float  v2 = __shfl_xor_sync(0xffffffffu, v, off);
            int    i2 = __shfl_xor_sync(0xffffffffu, idx, off);
            double s2 = __shfl_xor_sync(0xffffffffu, s, off);
            s += s2;
            if (v2 < v || (v2 == v && i2 < idx)) { v = v2; idx = i2; }
        }
        if (tcol == 0) {
            int row = row0 + trow * 8 + i;
            out[1 + row] = (float)idx;  // ynew
            lossp += s;                 // distance[row, y[row]]
        }
    }
    lred[tid] = lossp;
    __syncthreads();
    for (int sdiv = NT / 2; sdiv > 0; sdiv >>= 1) {
        if (tid < sdiv) lred[tid] += lred[tid + sdiv];
        __syncthreads();
    }
    if (tid == 0) atomicAdd(&g_loss, lred[0]);
}

// Kernel 3: write scalar loss; zero any padding in out.
__global__ void finalize_kernel(float* __restrict__ out, int out_size) {
    int t = blockIdx.x * blockDim.x + threadIdx.x;
    if (t == 0) out[0] = (float)g_loss;
    for (int i = 1 + NP + t; i < out_size; i += blockDim.x * gridDim.x) out[i] = 0.f;
}

extern "C" void kernel_launch(void* const* d_in, const int* in_sizes, int n_in,
                              void* d_out, int out_size) {
    const float* x = nullptr;
    const int*   y = nullptr;
    const float* cen = nullptr;
    for (int i = 0; i < n_in; i++) {
        if (in_sizes[i] == NP * DD)      x = (const float*)d_in[i];
        else if (in_sizes[i] == KC * DD) cen = (const float*)d_in[i];
        else if (in_sizes[i] == NP)      y = (const int*)d_in[i];
    }
    float* out = (float*)d_out;

    prep_kernel<<<256 + KC / 256, 256>>>(x, cen);
    kmeans_main<<<NP / BM, NT>>>(x, y, cen, out);
    finalize_kernel<<<1, 256>>>(out, out_size);
}